// round 15
// baseline (speedup 1.0000x reference)
#include <cuda_runtime.h>
#include <cuda_fp16.h>
#include <math_constants.h>

#define NN 50000
#define EE 850000

// ---------------- scratch (device globals; no allocation allowed) ----------
__device__ __half g_feat16[NN * 128];
__device__ float  g_h0[NN * 128];
__device__ float  g_h1[NN * 64];
__device__ float  g_el[NN * 2];
__device__ float  g_er[NN * 2];
__device__ int    g_src[EE];
__device__ int    g_dst[EE];
__device__ int    g_count[NN];
__device__ int    g_cursor[NN];
__device__ int    g_rowptr[NN + 1];
__device__ int    g_colsrc[EE];
__device__ int    g_bsum[64];
__device__ int    g_is64;

// ---------------- index width detection ------------------------------------
__global__ void detect_kernel(const unsigned* src_w, const unsigned* dst_w) {
    int i64 = 1;
    for (int k = 0; k < 16; k++) {
        if (src_w[2 * k + 1] != 0u) i64 = 0;
        if (dst_w[2 * k + 1] != 0u) i64 = 0;
    }
    g_is64 = i64;
}

__global__ void hist_kernel(const void* src, const void* dst) {
    int i = blockIdx.x * blockDim.x + threadIdx.x;
    if (i >= EE) return;
    int s, d;
    if (g_is64) {
        s = (int)((const long long*)src)[i];
        d = (int)((const long long*)dst)[i];
    } else {
        s = ((const int*)src)[i];
        d = ((const int*)dst)[i];
    }
    g_src[i] = s;
    g_dst[i] = d;
    atomicAdd(&g_count[d], 1);
}

// ---------------- 2-phase exclusive scan ------------------------------------
__global__ void scan_block_kernel() {
    __shared__ int wsum[32];
    int i = blockIdx.x * 1024 + threadIdx.x;
    int lane = threadIdx.x & 31, wid = threadIdx.x >> 5;
    int v = (i < NN) ? g_count[i] : 0;
    int incl = v;
#pragma unroll
    for (int off = 1; off < 32; off <<= 1) {
        int t = __shfl_up_sync(0xFFFFFFFFu, incl, off);
        if (lane >= off) incl += t;
    }
    if (lane == 31) wsum[wid] = incl;
    __syncthreads();
    if (wid == 0) {
        int s = wsum[lane];
        int si = s;
#pragma unroll
        for (int off = 1; off < 32; off <<= 1) {
            int t = __shfl_up_sync(0xFFFFFFFFu, si, off);
            if (lane >= off) si += t;
        }
        wsum[lane] = si - s;
        if (lane == 31) g_bsum[blockIdx.x] = si;
    }
    __syncthreads();
    if (i < NN) g_cursor[i] = incl - v + wsum[wid];
}

__global__ void scan_add_kernel(int nb) {
    __shared__ int soff[64];
    if (threadIdx.x == 0) {
        int acc = 0;
        for (int j = 0; j < nb; j++) { soff[j] = acc; acc += g_bsum[j]; }
    }
    __syncthreads();
    int i = blockIdx.x * blockDim.x + threadIdx.x;
    if (i < NN) {
        int r = g_cursor[i] + soff[i >> 10];
        g_rowptr[i] = r;
        g_cursor[i] = r;
    }
    if (i == 0) g_rowptr[NN] = EE;
}

__global__ void scatter_kernel() {
    int i = blockIdx.x * blockDim.x + threadIdx.x;
    if (i >= EE) return;
    int d = g_dst[i];
    int pos = atomicAdd(&g_cursor[d], 1);
    g_colsrc[pos] = g_src[i];
}

// ---------------- tiled GEMM: fp16 feat store + fused el/er epilogue --------
template <int FIN, int HD, int TM, int TX, int TY, int H>
__global__ void gemm_tiled_kernel(const float* __restrict__ x,
                                  const float* __restrict__ W,
                                  const float* __restrict__ al,
                                  const float* __restrict__ ar,
                                  __half* __restrict__ feat,
                                  float* __restrict__ el,
                                  float* __restrict__ er) {
    constexpr int NODES = TM * TY;
    constexpr int D = HD / H;
    extern __shared__ float sh[];
    float* Wsh = sh;                 // [FIN][HD]
    float* Xsh = sh + FIN * HD;      // [NODES][FIN]
    int node0 = blockIdx.x * NODES;
    int tid = threadIdx.x;

    for (int i = tid; i < FIN * HD / 4; i += TX * TY)
        ((float4*)Wsh)[i] = ((const float4*)W)[i];
    for (int i = tid; i < NODES * FIN / 4; i += TX * TY) {
        int n = i / (FIN / 4), k4 = i % (FIN / 4);
        int gn = node0 + n;
        ((float4*)Xsh)[i] = (gn < NN) ? ((const float4*)(x + (size_t)gn * FIN))[k4]
                                      : make_float4(0.f, 0.f, 0.f, 0.f);
    }
    __syncthreads();

    int tx = tid % TX, ty = tid / TX;
    float ac[TM][4];
#pragma unroll
    for (int m = 0; m < TM; m++)
#pragma unroll
        for (int n = 0; n < 4; n++) ac[m][n] = 0.f;

#pragma unroll 4
    for (int k = 0; k < FIN; k++) {
        float4 wv = ((float4*)(Wsh + k * HD))[tx];
#pragma unroll
        for (int m = 0; m < TM; m++) {
            float xv = Xsh[(ty * TM + m) * FIN + k];
            ac[m][0] += xv * wv.x;
            ac[m][1] += xv * wv.y;
            ac[m][2] += xv * wv.z;
            ac[m][3] += xv * wv.w;
        }
    }

    float4 alv = ((const float4*)al)[tx];
    float4 arv = ((const float4*)ar)[tx];
#pragma unroll
    for (int m = 0; m < TM; m++) {
        int node = node0 + ty * TM + m;
        float pl = ac[m][0] * alv.x + ac[m][1] * alv.y + ac[m][2] * alv.z + ac[m][3] * alv.w;
        float pr = ac[m][0] * arv.x + ac[m][1] * arv.y + ac[m][2] * arv.z + ac[m][3] * arv.w;
#pragma unroll
        for (int off = 8; off; off >>= 1) {
            pl += __shfl_xor_sync(0xFFFFFFFFu, pl, off);
            pr += __shfl_xor_sync(0xFFFFFFFFu, pr, off);
        }
        if (node < NN) {
            __half2 p0 = __floats2half2_rn(ac[m][0], ac[m][1]);
            __half2 p1 = __floats2half2_rn(ac[m][2], ac[m][3]);
            *(__half2*)(feat + (size_t)node * HD + 4 * tx)     = p0;
            *(__half2*)(feat + (size_t)node * HD + 4 * tx + 2) = p1;
            if ((tx & 15) == 0) {
                int h = (4 * tx) / D;
                el[node * H + h] = pl;
                er[node * H + h] = pr;
            }
        }
    }
}

// ---------------- small fused GEMM (layer 2 only: Fin=64, HD=40) -------------
__global__ void gemm_feat_kernel(const float* __restrict__ x,
                                 const float* __restrict__ W,
                                 const float* __restrict__ al,
                                 const float* __restrict__ ar,
                                 __half* __restrict__ feat,
                                 float* __restrict__ el,
                                 float* __restrict__ er,
                                 int Fin, int H, int D) {
    int gwarp = (blockIdx.x * blockDim.x + threadIdx.x) >> 5;
    int lane  = threadIdx.x & 31;
    if (gwarp >= NN) return;
    int HD  = H * D;
    int HD4 = HD >> 2;
    bool active = lane < HD4;

    const float* xrow = x + (size_t)gwarp * Fin;
    float xr[4];
#pragma unroll
    for (int w = 0; w < 4; w++) {
        int k = lane + 32 * w;
        xr[w] = (k < Fin) ? xrow[k] : 0.0f;
    }

    float a0 = 0.f, a1 = 0.f, a2 = 0.f, a3 = 0.f;
    const float4* W4 = (const float4*)W;
    for (int w = 0; w < 4; w++) {
        if (32 * w >= Fin) break;
        float xw = xr[w];
#pragma unroll
        for (int kk = 0; kk < 32; kk++) {
            float xk = __shfl_sync(0xFFFFFFFFu, xw, kk);
            if (active) {
                float4 wv = __ldg(&W4[(32 * w + kk) * HD4 + lane]);
                a0 += xk * wv.x; a1 += xk * wv.y;
                a2 += xk * wv.z; a3 += xk * wv.w;
            }
        }
    }

    float pl = 0.f, pr = 0.f;
    if (active) {
        __half2 p0 = __floats2half2_rn(a0, a1);
        __half2 p1 = __floats2half2_rn(a2, a3);
        *(__half2*)(feat + (size_t)gwarp * HD + 4 * lane)     = p0;
        *(__half2*)(feat + (size_t)gwarp * HD + 4 * lane + 2) = p1;
        int c = 4 * lane;
        pl = a0 * al[c] + a1 * al[c + 1] + a2 * al[c + 2] + a3 * al[c + 3];
        pr = a0 * ar[c] + a1 * ar[c + 1] + a2 * ar[c + 2] + a3 * ar[c + 3];
    }
#pragma unroll
    for (int off = 16; off; off >>= 1) {
        pl += __shfl_xor_sync(0xFFFFFFFFu, pl, off);
        pr += __shfl_xor_sync(0xFFFFFFFFu, pr, off);
    }
    if (lane == 0) { el[gwarp] = pl; er[gwarp] = pr; }
}

// ---------------- single-pass fused softmax + aggregation (fp16 gather) -----
// One node per warp (GPW=1 everywhere): HD/4 active lanes, no intra-warp
// divergence between node groups. 4 cols per lane (uint2 of halves).
template <int H, int D, int GPW>
__global__ void fused_attn_kernel(const __half* __restrict__ feat,
                                  const float* __restrict__ el,
                                  const float* __restrict__ er,
                                  const float* __restrict__ bias,
                                  float* __restrict__ out) {
    constexpr int HD  = H * D;
    constexpr int HD4 = HD / 4;
    int warp = (blockIdx.x * blockDim.x + threadIdx.x) >> 5;
    int lane = threadIdx.x & 31;
    int g    = lane / HD4;
    int sub  = lane - g * HD4;
    int node = warp * GPW + g;
    if (g >= GPW || node >= NN) return;

    const int h    = (4 * sub) / D;
    const float er_d = __ldg(&er[node * H + h]);
    const int e0 = g_rowptr[node];
    const int e1 = g_rowptr[node + 1];

    float ssum = 0.f;
    float ax = 0.f, ay = 0.f, az = 0.f, aw = 0.f;
#pragma unroll 4
    for (int e = e0; e < e1; e++) {
        int s   = __ldg(&g_colsrc[e]);
        float v = __ldg(&el[s * H + h]) + er_d;
        v = v > 0.f ? v : 0.2f * v;
        float p = __expf(v);
        uint2 raw = __ldg((const uint2*)(feat + (size_t)s * HD + 4 * sub));
        float2 f01 = __half22float2(*(const __half2*)&raw.x);
        float2 f23 = __half22float2(*(const __half2*)&raw.y);
        ax += p * f01.x;
        ay += p * f01.y;
        az += p * f23.x;
        aw += p * f23.y;
        ssum += p;
    }
    float inv = __frcp_rn(ssum);
    float4 o;
    o.x = ax * inv + __ldg(&bias[4 * sub + 0]);
    o.y = ay * inv + __ldg(&bias[4 * sub + 1]);
    o.z = az * inv + __ldg(&bias[4 * sub + 2]);
    o.w = aw * inv + __ldg(&bias[4 * sub + 3]);
    *(float4*)(out + (size_t)node * HD + 4 * sub) = o;
}

// ---------------- launcher ---------------------------------------------------
extern "C" void kernel_launch(void* const* d_in, const int* in_sizes, int n_in,
                              void* d_out, int out_size) {
    const float* in_feat = (const float*)d_in[0];
    const void*  src     = d_in[1];
    const void*  dst     = d_in[2];
    const float* W0 = (const float*)d_in[3];
    const float* al0 = (const float*)d_in[4];
    const float* ar0 = (const float*)d_in[5];
    const float* b0 = (const float*)d_in[6];
    const float* W1 = (const float*)d_in[7];
    const float* al1 = (const float*)d_in[8];
    const float* ar1 = (const float*)d_in[9];
    const float* b1 = (const float*)d_in[10];
    const float* W2 = (const float*)d_in[11];
    const float* al2 = (const float*)d_in[12];
    const float* ar2 = (const float*)d_in[13];
    const float* b2 = (const float*)d_in[14];
    float* out = (float*)d_out;

    __half* feat_p;
    float *h0_p, *h1_p, *el_p, *er_p;
    int* count_p;
    cudaGetSymbolAddress((void**)&feat_p, g_feat16);
    cudaGetSymbolAddress((void**)&h0_p, g_h0);
    cudaGetSymbolAddress((void**)&h1_p, g_h1);
    cudaGetSymbolAddress((void**)&el_p, g_el);
    cudaGetSymbolAddress((void**)&er_p, g_er);
    cudaGetSymbolAddress((void**)&count_p, g_count);

    constexpr int SMEM_L0 = (128 * 128 + 64 * 128) * 4;  // 96 KB
    constexpr int SMEM_L1 = (128 * 64 + 64 * 128) * 4;   // 64 KB
    cudaFuncSetAttribute(gemm_tiled_kernel<128, 128, 8, 32, 8, 2>,
                         cudaFuncAttributeMaxDynamicSharedMemorySize, SMEM_L0);
    cudaFuncSetAttribute(gemm_tiled_kernel<128, 64, 4, 16, 16, 1>,
                         cudaFuncAttributeMaxDynamicSharedMemorySize, SMEM_L1);

    // ---- try to insert GEMM0 as a root graph node (runs parallel to CSR) ----
    bool manual = false;
    cudaGraphNode_t gemm0_node;
    {
        cudaStreamCaptureStatus st = cudaStreamCaptureStatusNone;
        cudaGraph_t cgraph = nullptr;
        const cudaGraphNode_t* cdeps = nullptr;
        const cudaGraphEdgeData* cedges = nullptr;
        size_t nd = 0;
        unsigned long long cid = 0;
        if (cudaStreamGetCaptureInfo((cudaStream_t)0, &st, &cid, &cgraph,
                                     &cdeps, &cedges, &nd) == cudaSuccess &&
            st == cudaStreamCaptureStatusActive && cgraph != nullptr) {
            cudaKernelNodeParams p = {};
            const float* a_in = in_feat;
            const float* a_W = W0;
            const float* a_al = al0;
            const float* a_ar = ar0;
            __half* a_feat = feat_p;
            float* a_el = el_p;
            float* a_er = er_p;
            void* args[7] = {&a_in, &a_W, &a_al, &a_ar, &a_feat, &a_el, &a_er};
            p.func = (void*)gemm_tiled_kernel<128, 128, 8, 32, 8, 2>;
            p.gridDim = dim3((NN + 63) / 64, 1, 1);
            p.blockDim = dim3(256, 1, 1);
            p.sharedMemBytes = SMEM_L0;
            p.kernelParams = args;
            p.extra = nullptr;
            if (cudaGraphAddKernelNode(&gemm0_node, cgraph, nullptr, 0, &p)
                    == cudaSuccess)
                manual = true;
        }
    }

    // ---- CSR build chain (in-stream; overlaps with GEMM0) ----
    detect_kernel<<<1, 1>>>((const unsigned*)src, (const unsigned*)dst);
    cudaMemsetAsync(count_p, 0, NN * sizeof(int));
    hist_kernel<<<(EE + 255) / 256, 256>>>(src, dst);
    int nb = (NN + 1023) / 1024;
    scan_block_kernel<<<nb, 1024>>>();
    scan_add_kernel<<<(NN + 255) / 256, 256>>>(nb);
    scatter_kernel<<<(EE + 255) / 256, 256>>>();

    // ---- join GEMM0 into the stream (or launch it here if not capturing) ----
    if (manual) {
        cudaStreamUpdateCaptureDependencies((cudaStream_t)0, &gemm0_node,
                                            nullptr, 1,
                                            cudaStreamAddCaptureDependencies);
    } else {
        gemm_tiled_kernel<128, 128, 8, 32, 8, 2>
            <<<(NN + 63) / 64, 256, SMEM_L0>>>(in_feat, W0, al0, ar0,
                                               feat_p, el_p, er_p);
    }

    // ---- layer 0 edge phase: warp per node ----
    fused_attn_kernel<2, 64, 1>
        <<<(NN * 32 + 255) / 256, 256>>>(feat_p, el_p, er_p, b0, h0_p);

    // ---- layer 1: 128 -> 1 head x 64 ----
    gemm_tiled_kernel<128, 64, 4, 16, 16, 1>
        <<<(NN + 63) / 64, 256, SMEM_L1>>>(h0_p, W1, al1, ar1, feat_p, el_p, er_p);
    // warp per node (GPW=1): 16 active lanes, zero intra-warp divergence
    fused_attn_kernel<1, 64, 1>
        <<<(NN * 32 + 255) / 256, 256>>>(feat_p, el_p, er_p, b1, h1_p);

    // ---- layer 2: 64 -> 1 head x 40 -> d_out ----
    gemm_feat_kernel<<<(NN + 7) / 8, 256>>>(h1_p, W2, al2, ar2, feat_p, el_p, er_p, 64, 1, 40);
    // warp per node (GPW=1): 10 active lanes, zero intra-warp divergence
    fused_attn_kernel<1, 40, 1>
        <<<(NN * 32 + 255) / 256, 256>>>(feat_p, el_p, er_p, b2, out);
}

// round 16
// speedup vs baseline: 1.0937x; 1.0937x over previous
#include <cuda_runtime.h>
#include <cuda_fp16.h>
#include <math_constants.h>

#define NN 50000
#define EE 850000

// ---------------- scratch (device globals; no allocation allowed) ----------
__device__ __half g_feat16[NN * 128];
__device__ float  g_h0[NN * 128];
__device__ float  g_h1[NN * 64];
__device__ float  g_el[NN * 2];
__device__ float  g_er[NN * 2];
__device__ int    g_src[EE];
__device__ int    g_dst[EE];
__device__ int    g_count[NN];
__device__ int    g_cursor[NN];
__device__ int    g_rowptr[NN + 1];
__device__ int    g_colsrc[EE];
__device__ int    g_bsum[64];
__device__ int    g_is64;

// ---------------- index width detection ------------------------------------
__global__ void detect_kernel(const unsigned* src_w, const unsigned* dst_w) {
    int i64 = 1;
    for (int k = 0; k < 16; k++) {
        if (src_w[2 * k + 1] != 0u) i64 = 0;
        if (dst_w[2 * k + 1] != 0u) i64 = 0;
    }
    g_is64 = i64;
}

__global__ void hist_kernel(const void* src, const void* dst) {
    int i = blockIdx.x * blockDim.x + threadIdx.x;
    if (i >= EE) return;
    int s, d;
    if (g_is64) {
        s = (int)((const long long*)src)[i];
        d = (int)((const long long*)dst)[i];
    } else {
        s = ((const int*)src)[i];
        d = ((const int*)dst)[i];
    }
    g_src[i] = s;
    g_dst[i] = d;
    atomicAdd(&g_count[d], 1);
}

// ---------------- 2-phase exclusive scan ------------------------------------
__global__ void scan_block_kernel() {
    __shared__ int wsum[32];
    int i = blockIdx.x * 1024 + threadIdx.x;
    int lane = threadIdx.x & 31, wid = threadIdx.x >> 5;
    int v = (i < NN) ? g_count[i] : 0;
    int incl = v;
#pragma unroll
    for (int off = 1; off < 32; off <<= 1) {
        int t = __shfl_up_sync(0xFFFFFFFFu, incl, off);
        if (lane >= off) incl += t;
    }
    if (lane == 31) wsum[wid] = incl;
    __syncthreads();
    if (wid == 0) {
        int s = wsum[lane];
        int si = s;
#pragma unroll
        for (int off = 1; off < 32; off <<= 1) {
            int t = __shfl_up_sync(0xFFFFFFFFu, si, off);
            if (lane >= off) si += t;
        }
        wsum[lane] = si - s;
        if (lane == 31) g_bsum[blockIdx.x] = si;
    }
    __syncthreads();
    if (i < NN) g_cursor[i] = incl - v + wsum[wid];
}

// merged: every block redundantly scans the <=49 block sums, then applies.
__global__ void scan_add_kernel(int nb) {
    __shared__ int soff[64];
    if (threadIdx.x == 0) {
        int acc = 0;
        for (int j = 0; j < nb; j++) { soff[j] = acc; acc += g_bsum[j]; }
    }
    __syncthreads();
    int i = blockIdx.x * blockDim.x + threadIdx.x;
    if (i < NN) {
        int r = g_cursor[i] + soff[i >> 10];
        g_rowptr[i] = r;
        g_cursor[i] = r;
    }
    if (i == 0) g_rowptr[NN] = EE;
}

__global__ void scatter_kernel() {
    int i = blockIdx.x * blockDim.x + threadIdx.x;
    if (i >= EE) return;
    int d = g_dst[i];
    int pos = atomicAdd(&g_cursor[d], 1);
    g_colsrc[pos] = g_src[i];
}

// ---------------- tiled GEMM: fp16 feat store + fused el/er epilogue --------
template <int FIN, int HD, int TM, int TX, int TY, int H>
__global__ void gemm_tiled_kernel(const float* __restrict__ x,
                                  const float* __restrict__ W,
                                  const float* __restrict__ al,
                                  const float* __restrict__ ar,
                                  __half* __restrict__ feat,
                                  float* __restrict__ el,
                                  float* __restrict__ er) {
    constexpr int NODES = TM * TY;
    constexpr int D = HD / H;
    extern __shared__ float sh[];
    float* Wsh = sh;                 // [FIN][HD]
    float* Xsh = sh + FIN * HD;      // [NODES][FIN]
    int node0 = blockIdx.x * NODES;
    int tid = threadIdx.x;

    for (int i = tid; i < FIN * HD / 4; i += TX * TY)
        ((float4*)Wsh)[i] = ((const float4*)W)[i];
    for (int i = tid; i < NODES * FIN / 4; i += TX * TY) {
        int n = i / (FIN / 4), k4 = i % (FIN / 4);
        int gn = node0 + n;
        ((float4*)Xsh)[i] = (gn < NN) ? ((const float4*)(x + (size_t)gn * FIN))[k4]
                                      : make_float4(0.f, 0.f, 0.f, 0.f);
    }
    __syncthreads();

    int tx = tid % TX, ty = tid / TX;
    float ac[TM][4];
#pragma unroll
    for (int m = 0; m < TM; m++)
#pragma unroll
        for (int n = 0; n < 4; n++) ac[m][n] = 0.f;

#pragma unroll 4
    for (int k = 0; k < FIN; k++) {
        float4 wv = ((float4*)(Wsh + k * HD))[tx];
#pragma unroll
        for (int m = 0; m < TM; m++) {
            float xv = Xsh[(ty * TM + m) * FIN + k];
            ac[m][0] += xv * wv.x;
            ac[m][1] += xv * wv.y;
            ac[m][2] += xv * wv.z;
            ac[m][3] += xv * wv.w;
        }
    }

    float4 alv = ((const float4*)al)[tx];
    float4 arv = ((const float4*)ar)[tx];
#pragma unroll
    for (int m = 0; m < TM; m++) {
        int node = node0 + ty * TM + m;
        float pl = ac[m][0] * alv.x + ac[m][1] * alv.y + ac[m][2] * alv.z + ac[m][3] * alv.w;
        float pr = ac[m][0] * arv.x + ac[m][1] * arv.y + ac[m][2] * arv.z + ac[m][3] * arv.w;
#pragma unroll
        for (int off = 8; off; off >>= 1) {
            pl += __shfl_xor_sync(0xFFFFFFFFu, pl, off);
            pr += __shfl_xor_sync(0xFFFFFFFFu, pr, off);
        }
        if (node < NN) {
            __half2 p0 = __floats2half2_rn(ac[m][0], ac[m][1]);
            __half2 p1 = __floats2half2_rn(ac[m][2], ac[m][3]);
            *(__half2*)(feat + (size_t)node * HD + 4 * tx)     = p0;
            *(__half2*)(feat + (size_t)node * HD + 4 * tx + 2) = p1;
            if ((tx & 15) == 0) {
                int h = (4 * tx) / D;
                el[node * H + h] = pl;
                er[node * H + h] = pr;
            }
        }
    }
}

// ---------------- small fused GEMM (layer 2 only: Fin=64, HD=40) -------------
__global__ void gemm_feat_kernel(const float* __restrict__ x,
                                 const float* __restrict__ W,
                                 const float* __restrict__ al,
                                 const float* __restrict__ ar,
                                 __half* __restrict__ feat,
                                 float* __restrict__ el,
                                 float* __restrict__ er,
                                 int Fin, int H, int D) {
    int gwarp = (blockIdx.x * blockDim.x + threadIdx.x) >> 5;
    int lane  = threadIdx.x & 31;
    if (gwarp >= NN) return;
    int HD  = H * D;
    int HD4 = HD >> 2;
    bool active = lane < HD4;

    const float* xrow = x + (size_t)gwarp * Fin;
    float xr[4];
#pragma unroll
    for (int w = 0; w < 4; w++) {
        int k = lane + 32 * w;
        xr[w] = (k < Fin) ? xrow[k] : 0.0f;
    }

    float a0 = 0.f, a1 = 0.f, a2 = 0.f, a3 = 0.f;
    const float4* W4 = (const float4*)W;
    for (int w = 0; w < 4; w++) {
        if (32 * w >= Fin) break;
        float xw = xr[w];
#pragma unroll
        for (int kk = 0; kk < 32; kk++) {
            float xk = __shfl_sync(0xFFFFFFFFu, xw, kk);
            if (active) {
                float4 wv = __ldg(&W4[(32 * w + kk) * HD4 + lane]);
                a0 += xk * wv.x; a1 += xk * wv.y;
                a2 += xk * wv.z; a3 += xk * wv.w;
            }
        }
    }

    float pl = 0.f, pr = 0.f;
    if (active) {
        __half2 p0 = __floats2half2_rn(a0, a1);
        __half2 p1 = __floats2half2_rn(a2, a3);
        *(__half2*)(feat + (size_t)gwarp * HD + 4 * lane)     = p0;
        *(__half2*)(feat + (size_t)gwarp * HD + 4 * lane + 2) = p1;
        int c = 4 * lane;
        pl = a0 * al[c] + a1 * al[c + 1] + a2 * al[c + 2] + a3 * al[c + 3];
        pr = a0 * ar[c] + a1 * ar[c + 1] + a2 * ar[c + 2] + a3 * ar[c + 3];
    }
#pragma unroll
    for (int off = 16; off; off >>= 1) {
        pl += __shfl_xor_sync(0xFFFFFFFFu, pl, off);
        pr += __shfl_xor_sync(0xFFFFFFFFu, pr, off);
    }
    if (lane == 0) { el[gwarp] = pl; er[gwarp] = pr; }
}

// ---------------- single-pass fused softmax + aggregation (fp16 gather) -----
// R11 lane geometry: HD/4 lanes per node, 4 cols per lane (uint2 of halves).
template <int H, int D, int GPW>
__global__ void fused_attn_kernel(const __half* __restrict__ feat,
                                  const float* __restrict__ el,
                                  const float* __restrict__ er,
                                  const float* __restrict__ bias,
                                  float* __restrict__ out) {
    constexpr int HD  = H * D;
    constexpr int HD4 = HD / 4;
    int warp = (blockIdx.x * blockDim.x + threadIdx.x) >> 5;
    int lane = threadIdx.x & 31;
    int g    = lane / HD4;
    int sub  = lane - g * HD4;
    int node = warp * GPW + g;
    if (g >= GPW || node >= NN) return;

    const int h    = (4 * sub) / D;
    const float er_d = __ldg(&er[node * H + h]);
    const int e0 = g_rowptr[node];
    const int e1 = g_rowptr[node + 1];

    float ssum = 0.f;
    float ax = 0.f, ay = 0.f, az = 0.f, aw = 0.f;
#pragma unroll 4
    for (int e = e0; e < e1; e++) {
        int s   = __ldg(&g_colsrc[e]);
        float v = __ldg(&el[s * H + h]) + er_d;
        v = v > 0.f ? v : 0.2f * v;
        float p = __expf(v);
        uint2 raw = __ldg((const uint2*)(feat + (size_t)s * HD + 4 * sub));
        float2 f01 = __half22float2(*(const __half2*)&raw.x);
        float2 f23 = __half22float2(*(const __half2*)&raw.y);
        ax += p * f01.x;
        ay += p * f01.y;
        az += p * f23.x;
        aw += p * f23.y;
        ssum += p;
    }
    float inv = __frcp_rn(ssum);
    float4 o;
    o.x = ax * inv + __ldg(&bias[4 * sub + 0]);
    o.y = ay * inv + __ldg(&bias[4 * sub + 1]);
    o.z = az * inv + __ldg(&bias[4 * sub + 2]);
    o.w = aw * inv + __ldg(&bias[4 * sub + 3]);
    *(float4*)(out + (size_t)node * HD + 4 * sub) = o;
}

// ---------------- launcher ---------------------------------------------------
extern "C" void kernel_launch(void* const* d_in, const int* in_sizes, int n_in,
                              void* d_out, int out_size) {
    const float* in_feat = (const float*)d_in[0];
    const void*  src     = d_in[1];
    const void*  dst     = d_in[2];
    const float* W0 = (const float*)d_in[3];
    const float* al0 = (const float*)d_in[4];
    const float* ar0 = (const float*)d_in[5];
    const float* b0 = (const float*)d_in[6];
    const float* W1 = (const float*)d_in[7];
    const float* al1 = (const float*)d_in[8];
    const float* ar1 = (const float*)d_in[9];
    const float* b1 = (const float*)d_in[10];
    const float* W2 = (const float*)d_in[11];
    const float* al2 = (const float*)d_in[12];
    const float* ar2 = (const float*)d_in[13];
    const float* b2 = (const float*)d_in[14];
    float* out = (float*)d_out;

    __half* feat_p;
    float *h0_p, *h1_p, *el_p, *er_p;
    int* count_p;
    cudaGetSymbolAddress((void**)&feat_p, g_feat16);
    cudaGetSymbolAddress((void**)&h0_p, g_h0);
    cudaGetSymbolAddress((void**)&h1_p, g_h1);
    cudaGetSymbolAddress((void**)&el_p, g_el);
    cudaGetSymbolAddress((void**)&er_p, g_er);
    cudaGetSymbolAddress((void**)&count_p, g_count);

    constexpr int SMEM_L0 = (128 * 128 + 64 * 128) * 4;  // 96 KB
    constexpr int SMEM_L1 = (128 * 64 + 64 * 128) * 4;   // 64 KB
    cudaFuncSetAttribute(gemm_tiled_kernel<128, 128, 8, 32, 8, 2>,
                         cudaFuncAttributeMaxDynamicSharedMemorySize, SMEM_L0);
    cudaFuncSetAttribute(gemm_tiled_kernel<128, 64, 4, 16, 16, 1>,
                         cudaFuncAttributeMaxDynamicSharedMemorySize, SMEM_L1);

    // ---- try to insert GEMM0 as a root graph node (runs parallel to CSR) ----
    bool manual = false;
    cudaGraphNode_t gemm0_node;
    {
        cudaStreamCaptureStatus st = cudaStreamCaptureStatusNone;
        cudaGraph_t cgraph = nullptr;
        const cudaGraphNode_t* cdeps = nullptr;
        const cudaGraphEdgeData* cedges = nullptr;
        size_t nd = 0;
        unsigned long long cid = 0;
        if (cudaStreamGetCaptureInfo((cudaStream_t)0, &st, &cid, &cgraph,
                                     &cdeps, &cedges, &nd) == cudaSuccess &&
            st == cudaStreamCaptureStatusActive && cgraph != nullptr) {
            cudaKernelNodeParams p = {};
            const float* a_in = in_feat;
            const float* a_W = W0;
            const float* a_al = al0;
            const float* a_ar = ar0;
            __half* a_feat = feat_p;
            float* a_el = el_p;
            float* a_er = er_p;
            void* args[7] = {&a_in, &a_W, &a_al, &a_ar, &a_feat, &a_el, &a_er};
            p.func = (void*)gemm_tiled_kernel<128, 128, 8, 32, 8, 2>;
            p.gridDim = dim3((NN + 63) / 64, 1, 1);
            p.blockDim = dim3(256, 1, 1);
            p.sharedMemBytes = SMEM_L0;
            p.kernelParams = args;
            p.extra = nullptr;
            if (cudaGraphAddKernelNode(&gemm0_node, cgraph, nullptr, 0, &p)
                    == cudaSuccess)
                manual = true;
        }
    }

    // ---- CSR build chain (in-stream; overlaps with GEMM0) ----
    detect_kernel<<<1, 1>>>((const unsigned*)src, (const unsigned*)dst);
    cudaMemsetAsync(count_p, 0, NN * sizeof(int));
    hist_kernel<<<(EE + 255) / 256, 256>>>(src, dst);
    int nb = (NN + 1023) / 1024;
    scan_block_kernel<<<nb, 1024>>>();
    scan_add_kernel<<<(NN + 255) / 256, 256>>>(nb);
    scatter_kernel<<<(EE + 255) / 256, 256>>>();

    // ---- join GEMM0 into the stream (or launch it here if not capturing) ----
    if (manual) {
        cudaStreamUpdateCaptureDependencies((cudaStream_t)0, &gemm0_node,
                                            nullptr, 1,
                                            cudaStreamAddCaptureDependencies);
    } else {
        gemm_tiled_kernel<128, 128, 8, 32, 8, 2>
            <<<(NN + 63) / 64, 256, SMEM_L0>>>(in_feat, W0, al0, ar0,
                                               feat_p, el_p, er_p);
    }

    // ---- layer 0 edge phase: warp per node (GPW=1) ----
    fused_attn_kernel<2, 64, 1>
        <<<(NN * 32 + 255) / 256, 256>>>(feat_p, el_p, er_p, b0, h0_p);

    // ---- layer 1: 128 -> 1 head x 64 ----
    gemm_tiled_kernel<128, 64, 4, 16, 16, 1>
        <<<(NN + 63) / 64, 256, SMEM_L1>>>(h0_p, W1, al1, ar1, feat_p, el_p, er_p);
    {
        int warps = (NN + 1) / 2;
        fused_attn_kernel<1, 64, 2>
            <<<(warps * 32 + 255) / 256, 256>>>(feat_p, el_p, er_p, b1, h1_p);
    }

    // ---- layer 2: 64 -> 1 head x 40 -> d_out ----
    gemm_feat_kernel<<<(NN + 7) / 8, 256>>>(h1_p, W2, al2, ar2, feat_p, el_p, er_p, 64, 1, 40);
    {
        int warps = (NN + 2) / 3;
        fused_attn_kernel<1, 40, 3>
            <<<(warps * 32 + 255) / 256, 256>>>(feat_p, el_p, er_p, b2, out);
    }
}

// round 17
// speedup vs baseline: 1.1440x; 1.0460x over previous
#include <cuda_runtime.h>
#include <cuda_fp16.h>
#include <math_constants.h>

#define NN 50000
#define EE 850000

// ---------------- scratch (device globals; no allocation allowed) ----------
__device__ __half g_feat16[NN * 128];
__device__ __half g_h0[NN * 128];    // layer-0 output, fp16
__device__ __half g_h1[NN * 64];     // layer-1 output, fp16
__device__ float  g_el[NN * 2];
__device__ float  g_er[NN * 2];
__device__ int    g_src[EE];
__device__ int    g_dst[EE];
__device__ int    g_count[NN];
__device__ int    g_cursor[NN];
__device__ int    g_rowptr[NN + 1];
__device__ int    g_colsrc[EE];
__device__ int    g_bsum[64];
__device__ int    g_is64;

// ---------------- index width detection ------------------------------------
__global__ void detect_kernel(const unsigned* src_w, const unsigned* dst_w) {
    int i64 = 1;
    for (int k = 0; k < 16; k++) {
        if (src_w[2 * k + 1] != 0u) i64 = 0;
        if (dst_w[2 * k + 1] != 0u) i64 = 0;
    }
    g_is64 = i64;
}

__global__ void hist_kernel(const void* src, const void* dst) {
    int i = blockIdx.x * blockDim.x + threadIdx.x;
    if (i >= EE) return;
    int s, d;
    if (g_is64) {
        s = (int)((const long long*)src)[i];
        d = (int)((const long long*)dst)[i];
    } else {
        s = ((const int*)src)[i];
        d = ((const int*)dst)[i];
    }
    g_src[i] = s;
    g_dst[i] = d;
    atomicAdd(&g_count[d], 1);
}

// ---------------- 2-phase exclusive scan ------------------------------------
__global__ void scan_block_kernel() {
    __shared__ int wsum[32];
    int i = blockIdx.x * 1024 + threadIdx.x;
    int lane = threadIdx.x & 31, wid = threadIdx.x >> 5;
    int v = (i < NN) ? g_count[i] : 0;
    int incl = v;
#pragma unroll
    for (int off = 1; off < 32; off <<= 1) {
        int t = __shfl_up_sync(0xFFFFFFFFu, incl, off);
        if (lane >= off) incl += t;
    }
    if (lane == 31) wsum[wid] = incl;
    __syncthreads();
    if (wid == 0) {
        int s = wsum[lane];
        int si = s;
#pragma unroll
        for (int off = 1; off < 32; off <<= 1) {
            int t = __shfl_up_sync(0xFFFFFFFFu, si, off);
            if (lane >= off) si += t;
        }
        wsum[lane] = si - s;
        if (lane == 31) g_bsum[blockIdx.x] = si;
    }
    __syncthreads();
    if (i < NN) g_cursor[i] = incl - v + wsum[wid];
}

__global__ void scan_add_kernel(int nb) {
    __shared__ int soff[64];
    if (threadIdx.x == 0) {
        int acc = 0;
        for (int j = 0; j < nb; j++) { soff[j] = acc; acc += g_bsum[j]; }
    }
    __syncthreads();
    int i = blockIdx.x * blockDim.x + threadIdx.x;
    if (i < NN) {
        int r = g_cursor[i] + soff[i >> 10];
        g_rowptr[i] = r;
        g_cursor[i] = r;
    }
    if (i == 0) g_rowptr[NN] = EE;
}

__global__ void scatter_kernel() {
    int i = blockIdx.x * blockDim.x + threadIdx.x;
    if (i >= EE) return;
    int d = g_dst[i];
    int pos = atomicAdd(&g_cursor[d], 1);
    g_colsrc[pos] = g_src[i];
}

// ---------------- tiled GEMM: fp16 feat store + fused el/er epilogue --------
// XT = float (layer 0 input) or __half (layer 1 input = fp16 h0).
template <int FIN, int HD, int TM, int TX, int TY, int H, typename XT>
__global__ void gemm_tiled_kernel(const XT* __restrict__ x,
                                  const float* __restrict__ W,
                                  const float* __restrict__ al,
                                  const float* __restrict__ ar,
                                  __half* __restrict__ feat,
                                  float* __restrict__ el,
                                  float* __restrict__ er) {
    constexpr int NODES = TM * TY;
    constexpr int D = HD / H;
    extern __shared__ float sh[];
    float* Wsh = sh;                 // [FIN][HD]
    float* Xsh = sh + FIN * HD;      // [NODES][FIN]
    int node0 = blockIdx.x * NODES;
    int tid = threadIdx.x;

    for (int i = tid; i < FIN * HD / 4; i += TX * TY)
        ((float4*)Wsh)[i] = ((const float4*)W)[i];
    for (int i = tid; i < NODES * FIN / 4; i += TX * TY) {
        int n = i / (FIN / 4), k4 = i % (FIN / 4);
        int gn = node0 + n;
        float4 v;
        if (gn < NN) {
            if constexpr (sizeof(XT) == 2) {
                uint2 raw = ((const uint2*)(x + (size_t)gn * FIN))[k4];
                float2 a = __half22float2(*(const __half2*)&raw.x);
                float2 b = __half22float2(*(const __half2*)&raw.y);
                v = make_float4(a.x, a.y, b.x, b.y);
            } else {
                v = ((const float4*)(x + (size_t)gn * FIN))[k4];
            }
        } else {
            v = make_float4(0.f, 0.f, 0.f, 0.f);
        }
        ((float4*)Xsh)[i] = v;
    }
    __syncthreads();

    int tx = tid % TX, ty = tid / TX;
    float ac[TM][4];
#pragma unroll
    for (int m = 0; m < TM; m++)
#pragma unroll
        for (int n = 0; n < 4; n++) ac[m][n] = 0.f;

#pragma unroll 4
    for (int k = 0; k < FIN; k++) {
        float4 wv = ((float4*)(Wsh + k * HD))[tx];
#pragma unroll
        for (int m = 0; m < TM; m++) {
            float xv = Xsh[(ty * TM + m) * FIN + k];
            ac[m][0] += xv * wv.x;
            ac[m][1] += xv * wv.y;
            ac[m][2] += xv * wv.z;
            ac[m][3] += xv * wv.w;
        }
    }

    float4 alv = ((const float4*)al)[tx];
    float4 arv = ((const float4*)ar)[tx];
#pragma unroll
    for (int m = 0; m < TM; m++) {
        int node = node0 + ty * TM + m;
        float pl = ac[m][0] * alv.x + ac[m][1] * alv.y + ac[m][2] * alv.z + ac[m][3] * alv.w;
        float pr = ac[m][0] * arv.x + ac[m][1] * arv.y + ac[m][2] * arv.z + ac[m][3] * arv.w;
#pragma unroll
        for (int off = 8; off; off >>= 1) {
            pl += __shfl_xor_sync(0xFFFFFFFFu, pl, off);
            pr += __shfl_xor_sync(0xFFFFFFFFu, pr, off);
        }
        if (node < NN) {
            __half2 p0 = __floats2half2_rn(ac[m][0], ac[m][1]);
            __half2 p1 = __floats2half2_rn(ac[m][2], ac[m][3]);
            *(__half2*)(feat + (size_t)node * HD + 4 * tx)     = p0;
            *(__half2*)(feat + (size_t)node * HD + 4 * tx + 2) = p1;
            if ((tx & 15) == 0) {
                int h = (4 * tx) / D;
                el[node * H + h] = pl;
                er[node * H + h] = pr;
            }
        }
    }
}

// ---------------- small fused GEMM (layer 2 only: Fin=64, HD=40) -------------
// x is fp16 (h1).
__global__ void gemm_feat_kernel(const __half* __restrict__ x,
                                 const float* __restrict__ W,
                                 const float* __restrict__ al,
                                 const float* __restrict__ ar,
                                 __half* __restrict__ feat,
                                 float* __restrict__ el,
                                 float* __restrict__ er,
                                 int Fin, int H, int D) {
    int gwarp = (blockIdx.x * blockDim.x + threadIdx.x) >> 5;
    int lane  = threadIdx.x & 31;
    if (gwarp >= NN) return;
    int HD  = H * D;
    int HD4 = HD >> 2;
    bool active = lane < HD4;

    const __half* xrow = x + (size_t)gwarp * Fin;
    float xr[4];
#pragma unroll
    for (int w = 0; w < 4; w++) {
        int k = lane + 32 * w;
        xr[w] = (k < Fin) ? __half2float(xrow[k]) : 0.0f;
    }

    float a0 = 0.f, a1 = 0.f, a2 = 0.f, a3 = 0.f;
    const float4* W4 = (const float4*)W;
    for (int w = 0; w < 4; w++) {
        if (32 * w >= Fin) break;
        float xw = xr[w];
#pragma unroll
        for (int kk = 0; kk < 32; kk++) {
            float xk = __shfl_sync(0xFFFFFFFFu, xw, kk);
            if (active) {
                float4 wv = __ldg(&W4[(32 * w + kk) * HD4 + lane]);
                a0 += xk * wv.x; a1 += xk * wv.y;
                a2 += xk * wv.z; a3 += xk * wv.w;
            }
        }
    }

    float pl = 0.f, pr = 0.f;
    if (active) {
        __half2 p0 = __floats2half2_rn(a0, a1);
        __half2 p1 = __floats2half2_rn(a2, a3);
        *(__half2*)(feat + (size_t)gwarp * HD + 4 * lane)     = p0;
        *(__half2*)(feat + (size_t)gwarp * HD + 4 * lane + 2) = p1;
        int c = 4 * lane;
        pl = a0 * al[c] + a1 * al[c + 1] + a2 * al[c + 2] + a3 * al[c + 3];
        pr = a0 * ar[c] + a1 * ar[c + 1] + a2 * ar[c + 2] + a3 * ar[c + 3];
    }
#pragma unroll
    for (int off = 16; off; off >>= 1) {
        pl += __shfl_xor_sync(0xFFFFFFFFu, pl, off);
        pr += __shfl_xor_sync(0xFFFFFFFFu, pr, off);
    }
    if (lane == 0) { el[gwarp] = pl; er[gwarp] = pr; }
}

// ---------------- single-pass fused softmax + aggregation (fp16 gather) -----
// R11 lane geometry: HD/4 lanes per node, 4 cols per lane (uint2 of halves).
// OutT: __half for intermediate layers (h0/h1), float for final output.
template <int H, int D, int GPW, typename OutT>
__global__ void fused_attn_kernel(const __half* __restrict__ feat,
                                  const float* __restrict__ el,
                                  const float* __restrict__ er,
                                  const float* __restrict__ bias,
                                  OutT* __restrict__ out) {
    constexpr int HD  = H * D;
    constexpr int HD4 = HD / 4;
    int warp = (blockIdx.x * blockDim.x + threadIdx.x) >> 5;
    int lane = threadIdx.x & 31;
    int g    = lane / HD4;
    int sub  = lane - g * HD4;
    int node = warp * GPW + g;
    if (g >= GPW || node >= NN) return;

    const int h    = (4 * sub) / D;
    const float er_d = __ldg(&er[node * H + h]);
    const int e0 = g_rowptr[node];
    const int e1 = g_rowptr[node + 1];

    float ssum = 0.f;
    float ax = 0.f, ay = 0.f, az = 0.f, aw = 0.f;
#pragma unroll 4
    for (int e = e0; e < e1; e++) {
        int s   = __ldg(&g_colsrc[e]);
        float v = __ldg(&el[s * H + h]) + er_d;
        v = v > 0.f ? v : 0.2f * v;
        float p = __expf(v);
        uint2 raw = __ldg((const uint2*)(feat + (size_t)s * HD + 4 * sub));
        float2 f01 = __half22float2(*(const __half2*)&raw.x);
        float2 f23 = __half22float2(*(const __half2*)&raw.y);
        ax += p * f01.x;
        ay += p * f01.y;
        az += p * f23.x;
        aw += p * f23.y;
        ssum += p;
    }
    float inv = __frcp_rn(ssum);
    float o0 = ax * inv + __ldg(&bias[4 * sub + 0]);
    float o1 = ay * inv + __ldg(&bias[4 * sub + 1]);
    float o2 = az * inv + __ldg(&bias[4 * sub + 2]);
    float o3 = aw * inv + __ldg(&bias[4 * sub + 3]);
    if constexpr (sizeof(OutT) == 2) {
        __half2 p0 = __floats2half2_rn(o0, o1);
        __half2 p1 = __floats2half2_rn(o2, o3);
        uint2 packed;
        packed.x = *(unsigned*)&p0;
        packed.y = *(unsigned*)&p1;
        *(uint2*)((__half*)out + (size_t)node * HD + 4 * sub) = packed;
    } else {
        *(float4*)((float*)out + (size_t)node * HD + 4 * sub) =
            make_float4(o0, o1, o2, o3);
    }
}

// ---------------- launcher ---------------------------------------------------
extern "C" void kernel_launch(void* const* d_in, const int* in_sizes, int n_in,
                              void* d_out, int out_size) {
    const float* in_feat = (const float*)d_in[0];
    const void*  src     = d_in[1];
    const void*  dst     = d_in[2];
    const float* W0 = (const float*)d_in[3];
    const float* al0 = (const float*)d_in[4];
    const float* ar0 = (const float*)d_in[5];
    const float* b0 = (const float*)d_in[6];
    const float* W1 = (const float*)d_in[7];
    const float* al1 = (const float*)d_in[8];
    const float* ar1 = (const float*)d_in[9];
    const float* b1 = (const float*)d_in[10];
    const float* W2 = (const float*)d_in[11];
    const float* al2 = (const float*)d_in[12];
    const float* ar2 = (const float*)d_in[13];
    const float* b2 = (const float*)d_in[14];
    float* out = (float*)d_out;

    __half *feat_p, *h0_p, *h1_p;
    float *el_p, *er_p;
    int* count_p;
    cudaGetSymbolAddress((void**)&feat_p, g_feat16);
    cudaGetSymbolAddress((void**)&h0_p, g_h0);
    cudaGetSymbolAddress((void**)&h1_p, g_h1);
    cudaGetSymbolAddress((void**)&el_p, g_el);
    cudaGetSymbolAddress((void**)&er_p, g_er);
    cudaGetSymbolAddress((void**)&count_p, g_count);

    constexpr int SMEM_L0 = (128 * 128 + 64 * 128) * 4;  // 96 KB
    constexpr int SMEM_L1 = (128 * 64 + 64 * 128) * 4;   // 64 KB
    cudaFuncSetAttribute(gemm_tiled_kernel<128, 128, 8, 32, 8, 2, float>,
                         cudaFuncAttributeMaxDynamicSharedMemorySize, SMEM_L0);
    cudaFuncSetAttribute(gemm_tiled_kernel<128, 64, 4, 16, 16, 1, __half>,
                         cudaFuncAttributeMaxDynamicSharedMemorySize, SMEM_L1);

    // ---- try to insert GEMM0 as a root graph node (runs parallel to CSR) ----
    bool manual = false;
    cudaGraphNode_t gemm0_node;
    {
        cudaStreamCaptureStatus st = cudaStreamCaptureStatusNone;
        cudaGraph_t cgraph = nullptr;
        const cudaGraphNode_t* cdeps = nullptr;
        const cudaGraphEdgeData* cedges = nullptr;
        size_t nd = 0;
        unsigned long long cid = 0;
        if (cudaStreamGetCaptureInfo((cudaStream_t)0, &st, &cid, &cgraph,
                                     &cdeps, &cedges, &nd) == cudaSuccess &&
            st == cudaStreamCaptureStatusActive && cgraph != nullptr) {
            cudaKernelNodeParams p = {};
            const float* a_in = in_feat;
            const float* a_W = W0;
            const float* a_al = al0;
            const float* a_ar = ar0;
            __half* a_feat = feat_p;
            float* a_el = el_p;
            float* a_er = er_p;
            void* args[7] = {&a_in, &a_W, &a_al, &a_ar, &a_feat, &a_el, &a_er};
            p.func = (void*)gemm_tiled_kernel<128, 128, 8, 32, 8, 2, float>;
            p.gridDim = dim3((NN + 63) / 64, 1, 1);
            p.blockDim = dim3(256, 1, 1);
            p.sharedMemBytes = SMEM_L0;
            p.kernelParams = args;
            p.extra = nullptr;
            if (cudaGraphAddKernelNode(&gemm0_node, cgraph, nullptr, 0, &p)
                    == cudaSuccess)
                manual = true;
        }
    }

    // ---- CSR build chain (in-stream; overlaps with GEMM0) ----
    detect_kernel<<<1, 1>>>((const unsigned*)src, (const unsigned*)dst);
    cudaMemsetAsync(count_p, 0, NN * sizeof(int));
    hist_kernel<<<(EE + 255) / 256, 256>>>(src, dst);
    int nb = (NN + 1023) / 1024;
    scan_block_kernel<<<nb, 1024>>>();
    scan_add_kernel<<<(NN + 255) / 256, 256>>>(nb);
    scatter_kernel<<<(EE + 255) / 256, 256>>>();

    // ---- join GEMM0 into the stream (or launch it here if not capturing) ----
    if (manual) {
        cudaStreamUpdateCaptureDependencies((cudaStream_t)0, &gemm0_node,
                                            nullptr, 1,
                                            cudaStreamAddCaptureDependencies);
    } else {
        gemm_tiled_kernel<128, 128, 8, 32, 8, 2, float>
            <<<(NN + 63) / 64, 256, SMEM_L0>>>(in_feat, W0, al0, ar0,
                                               feat_p, el_p, er_p);
    }

    // ---- layer 0 edge phase: warp per node (GPW=1), fp16 h0 output ----
    fused_attn_kernel<2, 64, 1, __half>
        <<<(NN * 32 + 255) / 256, 256>>>(feat_p, el_p, er_p, b0, h0_p);

    // ---- layer 1: 128 -> 1 head x 64 (fp16 input) ----
    gemm_tiled_kernel<128, 64, 4, 16, 16, 1, __half>
        <<<(NN + 63) / 64, 256, SMEM_L1>>>(h0_p, W1, al1, ar1, feat_p, el_p, er_p);
    {
        int warps = (NN + 1) / 2;
        fused_attn_kernel<1, 64, 2, __half>
            <<<(warps * 32 + 255) / 256, 256>>>(feat_p, el_p, er_p, b1, h1_p);
    }

    // ---- layer 2: 64 -> 1 head x 40 -> d_out (fp32) ----
    gemm_feat_kernel<<<(NN + 7) / 8, 256>>>(h1_p, W2, al2, ar2, feat_p, el_p, er_p, 64, 1, 40);
    {
        int warps = (NN + 2) / 3;
        fused_attn_kernel<1, 40, 3, float>
            <<<(warps * 32 + 255) / 256, 256>>>(feat_p, el_p, er_p, b2, out);
    }
}